// round 2
// baseline (speedup 1.0000x reference)
#include <cuda_runtime.h>
#include <cuda_bf16.h>
#include <math.h>
#include <stdint.h>

#define BB 4
#define SS 2048
#define DD 1024
#define HH 16
#define HDD 64
#define M_TOT (BB*SS)          // 8192
#define N_QKV (3*DD)           // 3072

// Scratch (device globals: allocation-free)
__device__ float g_qkv[(size_t)M_TOT * N_QKV];   // [B*S, 3D]
__device__ float g_y[(size_t)M_TOT * DD];        // [B*S, D] attention output

// ---------------------------------------------------------------------------
// Tensor-core GEMM with fused bias, split-bf16 ("3x bf16") for fp32 accuracy.
// C[M,N] = A[M,K] @ W[K,N] + bias[N]
// 128x128 block tile, BK=32, 8 warps, warp tile 64x32 -> 4x4 m16n8k16 tiles.
// A = A_hi + A_lo (bf16 pair), product = hi*hi + hi*lo + lo*hi (fp32 accum).
// ---------------------------------------------------------------------------
#define AS_STRIDE 40   // bf16 elements; word = 20*r + q is conflict-free for quads

__device__ __forceinline__ void bf16_split(float x, __nv_bfloat16& h, __nv_bfloat16& l) {
    h = __float2bfloat16(x);
    l = __float2bfloat16(x - __bfloat162float(h));
}

__device__ __forceinline__ void mma_bf16(float* d,
    uint32_t a0, uint32_t a1, uint32_t a2, uint32_t a3,
    uint32_t b0, uint32_t b1)
{
    asm volatile(
        "mma.sync.aligned.m16n8k16.row.col.f32.bf16.bf16.f32 "
        "{%0,%1,%2,%3}, {%4,%5,%6,%7}, {%8,%9}, {%0,%1,%2,%3};\n"
        : "+f"(d[0]), "+f"(d[1]), "+f"(d[2]), "+f"(d[3])
        : "r"(a0), "r"(a1), "r"(a2), "r"(a3), "r"(b0), "r"(b1));
}

__global__ void __launch_bounds__(256) gemm_bias_tc(
    const float* __restrict__ A, const float* __restrict__ W,
    const float* __restrict__ bias, float* __restrict__ C,
    int M, int N, int K)
{
    __shared__ __nv_bfloat16 As_hi[128][AS_STRIDE];
    __shared__ __nv_bfloat16 As_lo[128][AS_STRIDE];
    __shared__ __nv_bfloat16 Bs_hi[128][AS_STRIDE];   // [n][k] (transposed)
    __shared__ __nv_bfloat16 Bs_lo[128][AS_STRIDE];

    const int tid  = threadIdx.x;
    const int lane = tid & 31;
    const int warp = tid >> 5;
    const int wm   = warp >> 2;          // 0..1
    const int wn   = warp & 3;           // 0..3
    const int bm   = blockIdx.y * 128;
    const int bn   = blockIdx.x * 128;

    // Global-load mapping
    const int ar = tid >> 3;             // 0..31 (A: 32 rows per pass, 4 passes)
    const int ac = (tid & 7) * 4;        // 0..28
    const int br = tid >> 5;             // 0..7  (B: 8 rows per pass, 4 passes)
    const int bc = (tid & 31) * 4;       // 0..124

    const float* Abase = A + (size_t)(bm + ar) * K + ac;
    const float* Wbase = W + (size_t)br * N + bn + bc;

    float4 pa[4], pb[4];

    // prefetch first tile
    #pragma unroll
    for (int i = 0; i < 4; i++)
        pa[i] = *(const float4*)(Abase + (size_t)(32 * i) * K);
    #pragma unroll
    for (int i = 0; i < 4; i++)
        pb[i] = *(const float4*)(Wbase + (size_t)(8 * i) * N);

    float acc[4][4][4];
    #pragma unroll
    for (int mt = 0; mt < 4; mt++)
        #pragma unroll
        for (int nt = 0; nt < 4; nt++)
            #pragma unroll
            for (int r = 0; r < 4; r++) acc[mt][nt][r] = 0.0f;

    for (int k0 = 0; k0 < K; k0 += 32) {
        // ---- convert + store prefetched tile to smem ----
        #pragma unroll
        for (int i = 0; i < 4; i++) {
            int row = ar + 32 * i;
            __nv_bfloat16 h, l;
            bf16_split(pa[i].x, h, l); As_hi[row][ac+0] = h; As_lo[row][ac+0] = l;
            bf16_split(pa[i].y, h, l); As_hi[row][ac+1] = h; As_lo[row][ac+1] = l;
            bf16_split(pa[i].z, h, l); As_hi[row][ac+2] = h; As_lo[row][ac+2] = l;
            bf16_split(pa[i].w, h, l); As_hi[row][ac+3] = h; As_lo[row][ac+3] = l;
        }
        #pragma unroll
        for (int i = 0; i < 4; i++) {
            int krow = br + 8 * i;
            __nv_bfloat16 h, l;
            bf16_split(pb[i].x, h, l); Bs_hi[bc+0][krow] = h; Bs_lo[bc+0][krow] = l;
            bf16_split(pb[i].y, h, l); Bs_hi[bc+1][krow] = h; Bs_lo[bc+1][krow] = l;
            bf16_split(pb[i].z, h, l); Bs_hi[bc+2][krow] = h; Bs_lo[bc+2][krow] = l;
            bf16_split(pb[i].w, h, l); Bs_hi[bc+3][krow] = h; Bs_lo[bc+3][krow] = l;
        }
        __syncthreads();

        // ---- prefetch next tile (overlaps with MMA work below) ----
        if (k0 + 32 < K) {
            #pragma unroll
            for (int i = 0; i < 4; i++)
                pa[i] = *(const float4*)(Abase + (size_t)(32 * i) * K + (k0 + 32));
            #pragma unroll
            for (int i = 0; i < 4; i++)
                pb[i] = *(const float4*)(Wbase + (size_t)(8 * i + k0 + 32) * N);
        }

        // ---- MMA over the two k16 steps ----
        #pragma unroll
        for (int kk = 0; kk < 32; kk += 16) {
            const int kq = kk + (lane & 3) * 2;
            uint32_t bh[4][2], bl[4][2];
            #pragma unroll
            for (int nt = 0; nt < 4; nt++) {
                int n = wn * 32 + nt * 8 + (lane >> 2);
                bh[nt][0] = *(const uint32_t*)&Bs_hi[n][kq];
                bh[nt][1] = *(const uint32_t*)&Bs_hi[n][kq + 8];
                bl[nt][0] = *(const uint32_t*)&Bs_lo[n][kq];
                bl[nt][1] = *(const uint32_t*)&Bs_lo[n][kq + 8];
            }
            #pragma unroll
            for (int mt = 0; mt < 4; mt++) {
                int r = wm * 64 + mt * 16 + (lane >> 2);
                uint32_t ah0 = *(const uint32_t*)&As_hi[r][kq];
                uint32_t ah1 = *(const uint32_t*)&As_hi[r + 8][kq];
                uint32_t ah2 = *(const uint32_t*)&As_hi[r][kq + 8];
                uint32_t ah3 = *(const uint32_t*)&As_hi[r + 8][kq + 8];
                uint32_t al0 = *(const uint32_t*)&As_lo[r][kq];
                uint32_t al1 = *(const uint32_t*)&As_lo[r + 8][kq];
                uint32_t al2 = *(const uint32_t*)&As_lo[r][kq + 8];
                uint32_t al3 = *(const uint32_t*)&As_lo[r + 8][kq + 8];
                #pragma unroll
                for (int nt = 0; nt < 4; nt++)
                    mma_bf16(acc[mt][nt], ah0, ah1, ah2, ah3, bh[nt][0], bh[nt][1]);
                #pragma unroll
                for (int nt = 0; nt < 4; nt++)
                    mma_bf16(acc[mt][nt], ah0, ah1, ah2, ah3, bl[nt][0], bl[nt][1]);
                #pragma unroll
                for (int nt = 0; nt < 4; nt++)
                    mma_bf16(acc[mt][nt], al0, al1, al2, al3, bh[nt][0], bh[nt][1]);
            }
        }
        __syncthreads();
    }

    // ---- epilogue: add bias, write fp32 ----
    #pragma unroll
    for (int mt = 0; mt < 4; mt++) {
        int r = bm + wm * 64 + mt * 16 + (lane >> 2);
        #pragma unroll
        for (int nt = 0; nt < 4; nt++) {
            int cidx = bn + wn * 32 + nt * 8 + (lane & 3) * 2;
            float2 bv = *(const float2*)&bias[cidx];
            float2 o0 = { acc[mt][nt][0] + bv.x, acc[mt][nt][1] + bv.y };
            float2 o1 = { acc[mt][nt][2] + bv.x, acc[mt][nt][3] + bv.y };
            *(float2*)&C[(size_t)r * N + cidx]       = o0;
            *(float2*)&C[(size_t)(r + 8) * N + cidx] = o1;
        }
    }
}

// ---------------------------------------------------------------------------
// Flash attention (causal), fp32 (unchanged from round 1).
// ---------------------------------------------------------------------------
#define QS_OFF   0
#define KT_OFF   (64 * 65)
#define VS_OFF   (2 * 64 * 65)
#define PS_OFF   (2 * 64 * 65 + 64 * 64)
#define SMEM_FLOATS (2 * 64 * 65 + 64 * 64 + 64 * 65)   // 16576 floats = 66304 B

__global__ void __launch_bounds__(256) flash_attn_kernel(
    const float* __restrict__ qkv, float* __restrict__ y)
{
    extern __shared__ float sm[];
    float* Qs = sm + QS_OFF;
    float* Kt = sm + KT_OFF;
    float* Vs = sm + VS_OFF;
    float* Ps = sm + PS_OFF;

    const int qb = blockIdx.x;
    const int h  = blockIdx.y;
    const int b  = blockIdx.z;
    const int tid = threadIdx.x;
    const int tx = tid & 15, ty = tid >> 4;
    const int r0 = ty * 4;
    const float scale = 0.125f;   // 1/sqrt(64)

    {
        const int lr = tid >> 2;
        const int lcb = (tid & 3) * 16;
        const float* gq = qkv + ((size_t)(b * SS + qb * 64 + lr)) * N_QKV + h * HDD + lcb;
        #pragma unroll
        for (int i = 0; i < 4; i++) {
            float4 v = *(const float4*)(gq + 4 * i);
            float* qs = &Qs[lr * 65 + lcb + 4 * i];
            qs[0] = v.x * scale; qs[1] = v.y * scale;
            qs[2] = v.z * scale; qs[3] = v.w * scale;
        }
    }

    float acc[4][4];
    float m_i[4], l_i[4];
    #pragma unroll
    for (int i = 0; i < 4; i++) {
        m_i[i] = -1e30f; l_i[i] = 0.0f;
        #pragma unroll
        for (int j = 0; j < 4; j++) acc[i][j] = 0.0f;
    }

    for (int kb = 0; kb <= qb; kb++) {
        {
            const int lr = tid >> 2;
            const int lcb = (tid & 3) * 16;
            const float* kg = qkv + ((size_t)(b * SS + kb * 64 + lr)) * N_QKV + h * HDD + DD + lcb;
            const float* vg = kg + DD;
            #pragma unroll
            for (int i = 0; i < 4; i++) {
                float4 kv4 = *(const float4*)(kg + 4 * i);
                Kt[(lcb + 4 * i + 0) * 65 + lr] = kv4.x;
                Kt[(lcb + 4 * i + 1) * 65 + lr] = kv4.y;
                Kt[(lcb + 4 * i + 2) * 65 + lr] = kv4.z;
                Kt[(lcb + 4 * i + 3) * 65 + lr] = kv4.w;
                float4 vv = *(const float4*)(vg + 4 * i);
                *(float4*)(&Vs[lr * 64 + lcb + 4 * i]) = vv;
            }
        }
        __syncthreads();

        float sv[4][4];
        #pragma unroll
        for (int i = 0; i < 4; i++)
            #pragma unroll
            for (int j = 0; j < 4; j++) sv[i][j] = 0.0f;

        #pragma unroll 16
        for (int k = 0; k < 64; k++) {
            float a[4], bb2[4];
            #pragma unroll
            for (int i = 0; i < 4; i++) a[i] = Qs[(r0 + i) * 65 + k];
            #pragma unroll
            for (int j = 0; j < 4; j++) bb2[j] = Kt[k * 65 + tx + 16 * j];
            #pragma unroll
            for (int i = 0; i < 4; i++)
                #pragma unroll
                for (int j = 0; j < 4; j++)
                    sv[i][j] += a[i] * bb2[j];
        }

        if (kb == qb) {
            #pragma unroll
            for (int i = 0; i < 4; i++)
                #pragma unroll
                for (int j = 0; j < 4; j++)
                    if (tx + 16 * j > r0 + i) sv[i][j] = -1e30f;
        }

        #pragma unroll
        for (int i = 0; i < 4; i++) {
            float mx = fmaxf(fmaxf(sv[i][0], sv[i][1]), fmaxf(sv[i][2], sv[i][3]));
            #pragma unroll
            for (int o = 8; o >= 1; o >>= 1)
                mx = fmaxf(mx, __shfl_xor_sync(0xffffffffu, mx, o));
            float mnew = fmaxf(m_i[i], mx);
            float p0 = __expf(sv[i][0] - mnew);
            float p1 = __expf(sv[i][1] - mnew);
            float p2 = __expf(sv[i][2] - mnew);
            float p3 = __expf(sv[i][3] - mnew);
            float ps = p0 + p1 + p2 + p3;
            #pragma unroll
            for (int o = 8; o >= 1; o >>= 1)
                ps += __shfl_xor_sync(0xffffffffu, ps, o);
            float alpha = __expf(m_i[i] - mnew);
            l_i[i] = l_i[i] * alpha + ps;
            m_i[i] = mnew;
            acc[i][0] *= alpha; acc[i][1] *= alpha;
            acc[i][2] *= alpha; acc[i][3] *= alpha;
            Ps[(r0 + i) * 65 + tx]      = p0;
            Ps[(r0 + i) * 65 + tx + 16] = p1;
            Ps[(r0 + i) * 65 + tx + 32] = p2;
            Ps[(r0 + i) * 65 + tx + 48] = p3;
        }
        __syncthreads();

        #pragma unroll 16
        for (int j = 0; j < 64; j++) {
            float p[4], v[4];
            #pragma unroll
            for (int i = 0; i < 4; i++) p[i] = Ps[(r0 + i) * 65 + j];
            #pragma unroll
            for (int c = 0; c < 4; c++) v[c] = Vs[j * 64 + tx + 16 * c];
            #pragma unroll
            for (int i = 0; i < 4; i++)
                #pragma unroll
                for (int c = 0; c < 4; c++)
                    acc[i][c] += p[i] * v[c];
        }
        __syncthreads();
    }

    #pragma unroll
    for (int i = 0; i < 4; i++) {
        float inv = 1.0f / l_i[i];
        float* yr = y + ((size_t)(b * SS + qb * 64 + r0 + i)) * DD + h * HDD;
        yr[tx]      = acc[i][0] * inv;
        yr[tx + 16] = acc[i][1] * inv;
        yr[tx + 32] = acc[i][2] * inv;
        yr[tx + 48] = acc[i][3] * inv;
    }
}

// ---------------------------------------------------------------------------
extern "C" void kernel_launch(void* const* d_in, const int* in_sizes, int n_in,
                              void* d_out, int out_size)
{
    const float* x      = (const float*)d_in[0];
    const float* W_attn = (const float*)d_in[1];
    const float* b_attn = (const float*)d_in[2];
    const float* W_proj = (const float*)d_in[3];
    const float* b_proj = (const float*)d_in[4];
    float* out = (float*)d_out;

    float* qkv = nullptr;
    float* yb  = nullptr;
    cudaGetSymbolAddress((void**)&qkv, g_qkv);
    cudaGetSymbolAddress((void**)&yb,  g_y);

    cudaFuncSetAttribute(flash_attn_kernel,
                         cudaFuncAttributeMaxDynamicSharedMemorySize,
                         SMEM_FLOATS * sizeof(float));

    // 1) QKV projection: [8192,1024] @ [1024,3072] + bias
    {
        dim3 grid(N_QKV / 128, M_TOT / 128);
        gemm_bias_tc<<<grid, 256>>>(x, W_attn, b_attn, qkv, M_TOT, N_QKV, DD);
    }

    // 2) causal flash attention -> y [8192, 1024]
    {
        dim3 grid(SS / 64, HH, BB);
        flash_attn_kernel<<<grid, 256, SMEM_FLOATS * sizeof(float)>>>(qkv, yb);
    }

    // 3) output projection: [8192,1024] @ [1024,1024] + bias -> out
    {
        dim3 grid(DD / 128, M_TOT / 128);
        gemm_bias_tc<<<grid, 256>>>(yb, W_proj, b_proj, out, M_TOT, DD, DD);
    }
}

// round 3
// speedup vs baseline: 1.5756x; 1.5756x over previous
#include <cuda_runtime.h>
#include <cuda_bf16.h>
#include <math.h>
#include <stdint.h>

#define BB 4
#define SS 2048
#define DD 1024
#define HH 16
#define HDD 64
#define M_TOT (BB*SS)          // 8192
#define N_QKV (3*DD)           // 3072

// ---------------- device scratch (allocation-free) ----------------
__device__ float g_qkv[(size_t)M_TOT * N_QKV];   // [B*S, 3D] fp32
__device__ float g_y[(size_t)M_TOT * DD];        // [B*S, D]  fp32

__device__ __nv_bfloat16 g_x_hi[(size_t)M_TOT * DD];
__device__ __nv_bfloat16 g_x_lo[(size_t)M_TOT * DD];
__device__ __nv_bfloat16 g_wa_hi[(size_t)DD * N_QKV];
__device__ __nv_bfloat16 g_wa_lo[(size_t)DD * N_QKV];
__device__ __nv_bfloat16 g_wp_hi[(size_t)DD * DD];
__device__ __nv_bfloat16 g_wp_lo[(size_t)DD * DD];
__device__ __nv_bfloat16 g_y_hi[(size_t)M_TOT * DD];
__device__ __nv_bfloat16 g_y_lo[(size_t)M_TOT * DD];

// ---------------- small PTX helpers ----------------
__device__ __forceinline__ void cp16(uint32_t dst, const void* src) {
    asm volatile("cp.async.cg.shared.global [%0], [%1], 16;" :: "r"(dst), "l"(src));
}
#define CP_COMMIT() asm volatile("cp.async.commit_group;")
#define CP_WAIT0()  asm volatile("cp.async.wait_group 0;")

__device__ __forceinline__ void ldsm_x4(uint32_t addr,
    uint32_t& r0, uint32_t& r1, uint32_t& r2, uint32_t& r3) {
    asm volatile("ldmatrix.sync.aligned.m8n8.x4.shared.b16 {%0,%1,%2,%3}, [%4];"
        : "=r"(r0), "=r"(r1), "=r"(r2), "=r"(r3) : "r"(addr));
}
__device__ __forceinline__ void ldsm_x4_t(uint32_t addr,
    uint32_t& r0, uint32_t& r1, uint32_t& r2, uint32_t& r3) {
    asm volatile("ldmatrix.sync.aligned.m8n8.x4.trans.shared.b16 {%0,%1,%2,%3}, [%4];"
        : "=r"(r0), "=r"(r1), "=r"(r2), "=r"(r3) : "r"(addr));
}
__device__ __forceinline__ void mma_bf16(float* d,
    uint32_t a0, uint32_t a1, uint32_t a2, uint32_t a3,
    uint32_t b0, uint32_t b1)
{
    asm volatile(
        "mma.sync.aligned.m16n8k16.row.col.f32.bf16.bf16.f32 "
        "{%0,%1,%2,%3}, {%4,%5,%6,%7}, {%8,%9}, {%0,%1,%2,%3};\n"
        : "+f"(d[0]), "+f"(d[1]), "+f"(d[2]), "+f"(d[3])
        : "r"(a0), "r"(a1), "r"(a2), "r"(a3), "r"(b0), "r"(b1));
}

// ---------------- split pass: fp32 -> (bf16 hi, bf16 lo) ----------------
__global__ void __launch_bounds__(256) split_kernel(
    const float* __restrict__ in,
    __nv_bfloat16* __restrict__ hi, __nv_bfloat16* __restrict__ lo, int n4)
{
    int i = blockIdx.x * blockDim.x + threadIdx.x;
    if (i >= n4) return;
    float4 v = ((const float4*)in)[i];
    __nv_bfloat16 h0 = __float2bfloat16(v.x); __nv_bfloat16 l0 = __float2bfloat16(v.x - __bfloat162float(h0));
    __nv_bfloat16 h1 = __float2bfloat16(v.y); __nv_bfloat16 l1 = __float2bfloat16(v.y - __bfloat162float(h1));
    __nv_bfloat16 h2 = __float2bfloat16(v.z); __nv_bfloat16 l2 = __float2bfloat16(v.z - __bfloat162float(h2));
    __nv_bfloat16 h3 = __float2bfloat16(v.w); __nv_bfloat16 l3 = __float2bfloat16(v.w - __bfloat162float(h3));
    ((__nv_bfloat162*)hi)[2*i]   = __nv_bfloat162(h0, h1);
    ((__nv_bfloat162*)hi)[2*i+1] = __nv_bfloat162(h2, h3);
    ((__nv_bfloat162*)lo)[2*i]   = __nv_bfloat162(l0, l1);
    ((__nv_bfloat162*)lo)[2*i+1] = __nv_bfloat162(l2, l3);
}

// ---------------------------------------------------------------------------
// Tensor-core split-bf16 GEMM: C = Ahi+Alo @ Whi+Wlo (3 products) + bias
// 128x128x32 tiles, 8 warps (2x4), cp.async double buffer, ldmatrix frags.
// smem layout per stage (bf16 elems):
//   Ah [128][40], Al [128][40]  (row m, col k; stride 40)
//   Bh [32][136], Bl [32][136]  (row k, col n; stride 136)
// ---------------------------------------------------------------------------
#define A_STR 40
#define B_STR 136
#define AH_OFF 0
#define AL_OFF (128*A_STR)                 // 5120
#define BH_OFF (2*128*A_STR)               // 10240
#define BL_OFF (2*128*A_STR + 32*B_STR)    // 14592
#define STAGE_ELEMS (2*128*A_STR + 2*32*B_STR)   // 18944 elems = 37888 B
#define GEMM_SMEM_BYTES (2 * STAGE_ELEMS * 2)    // 75776 B

__global__ void __launch_bounds__(256, 2) gemm_bias_tc(
    const __nv_bfloat16* __restrict__ Ahi, const __nv_bfloat16* __restrict__ Alo,
    const __nv_bfloat16* __restrict__ Whi, const __nv_bfloat16* __restrict__ Wlo,
    const float* __restrict__ bias, float* __restrict__ C,
    int M, int N, int K)
{
    extern __shared__ __nv_bfloat16 smem[];
    const uint32_t smem_u32 = (uint32_t)__cvta_generic_to_shared(smem);

    const int tid  = threadIdx.x;
    const int lane = tid & 31;
    const int warp = tid >> 5;
    const int wm   = warp >> 2;          // 0..1
    const int wn   = warp & 3;           // 0..3
    const int bm   = blockIdx.y * 128;
    const int bn   = blockIdx.x * 128;

    // cp.async mappings
    const int ar = tid >> 1;             // A row 0..127
    const int aj = (tid & 1) * 16;       // A col elem offset (two 8-elem chunks)
    const int kr = tid >> 3;             // B row (k) 0..31
    const int bj = (tid & 7) * 16;       // B col elem offset (two 8-elem chunks)

    const __nv_bfloat16* Ahi_g = Ahi + (size_t)(bm + ar) * K + aj;
    const __nv_bfloat16* Alo_g = Alo + (size_t)(bm + ar) * K + aj;
    const __nv_bfloat16* Whi_g = Whi + (size_t)kr * N + bn + bj;
    const __nv_bfloat16* Wlo_g = Wlo + (size_t)kr * N + bn + bj;

    const uint32_t a_sm = smem_u32 + (ar * A_STR + aj) * 2;
    const uint32_t b_sm = smem_u32 + (kr * B_STR + bj) * 2;

    auto issue_stage = [&](int k0, int s) {
        const uint32_t so = (uint32_t)(s * STAGE_ELEMS * 2);
        cp16(so + a_sm + AH_OFF*2,      Ahi_g + k0);
        cp16(so + a_sm + AH_OFF*2 + 16, Ahi_g + k0 + 8);
        cp16(so + a_sm + AL_OFF*2,      Alo_g + k0);
        cp16(so + a_sm + AL_OFF*2 + 16, Alo_g + k0 + 8);
        cp16(so + b_sm + BH_OFF*2,      Whi_g + (size_t)k0 * N);
        cp16(so + b_sm + BH_OFF*2 + 16, Whi_g + (size_t)k0 * N + 8);
        cp16(so + b_sm + BL_OFF*2,      Wlo_g + (size_t)k0 * N);
        cp16(so + b_sm + BL_OFF*2 + 16, Wlo_g + (size_t)k0 * N + 8);
        CP_COMMIT();
    };

    float acc[4][4][4];
    #pragma unroll
    for (int mt = 0; mt < 4; mt++)
        #pragma unroll
        for (int nt = 0; nt < 4; nt++)
            #pragma unroll
            for (int r = 0; r < 4; r++) acc[mt][nt][r] = 0.0f;

    // ldmatrix lane addressing (element indices)
    const int a_row_in = (lane & 7) + ((lane >> 3) & 1) * 8;   // within m16
    const int a_kcol   = (lane >> 4) * 8;                       // 0 or 8
    const int b_krow   = ((lane >> 3) & 1) * 8 + (lane & 7);    // within k16
    const int b_ncol   = (lane >> 4) * 8;                       // 0 or 8

    issue_stage(0, 0);

    const int nt_iters = K / 32;
    for (int t = 0; t < nt_iters; t++) {
        CP_WAIT0();
        __syncthreads();
        if (t + 1 < nt_iters) issue_stage((t + 1) * 32, (t + 1) & 1);

        const uint32_t so = (uint32_t)((t & 1) * STAGE_ELEMS * 2);
        const uint32_t ah_base = smem_u32 + so + AH_OFF * 2;
        const uint32_t al_base = smem_u32 + so + AL_OFF * 2;
        const uint32_t bh_base = smem_u32 + so + BH_OFF * 2;
        const uint32_t bl_base = smem_u32 + so + BL_OFF * 2;

        #pragma unroll
        for (int kk = 0; kk < 32; kk += 16) {
            // ---- B fragments: 2 ldmatrix.x4.trans per matrix (hi/lo) ----
            uint32_t bh[4][2], bl[4][2];
            #pragma unroll
            for (int p = 0; p < 2; p++) {
                const uint32_t baddr = (uint32_t)(((kk + b_krow) * B_STR +
                                       wn * 32 + p * 16 + b_ncol) * 2);
                ldsm_x4_t(bh_base + baddr, bh[2*p][0], bh[2*p][1], bh[2*p+1][0], bh[2*p+1][1]);
                ldsm_x4_t(bl_base + baddr, bl[2*p][0], bl[2*p][1], bl[2*p+1][0], bl[2*p+1][1]);
            }
            // ---- A fragments per mt, then 12 MMAs ----
            #pragma unroll
            for (int mt = 0; mt < 4; mt++) {
                const uint32_t aaddr = (uint32_t)(((wm * 64 + mt * 16 + a_row_in) * A_STR +
                                       kk + a_kcol) * 2);
                uint32_t ah0, ah1, ah2, ah3, al0, al1, al2, al3;
                ldsm_x4(ah_base + aaddr, ah0, ah1, ah2, ah3);
                ldsm_x4(al_base + aaddr, al0, al1, al2, al3);
                #pragma unroll
                for (int nt = 0; nt < 4; nt++)
                    mma_bf16(acc[mt][nt], ah0, ah1, ah2, ah3, bh[nt][0], bh[nt][1]);
                #pragma unroll
                for (int nt = 0; nt < 4; nt++)
                    mma_bf16(acc[mt][nt], ah0, ah1, ah2, ah3, bl[nt][0], bl[nt][1]);
                #pragma unroll
                for (int nt = 0; nt < 4; nt++)
                    mma_bf16(acc[mt][nt], al0, al1, al2, al3, bh[nt][0], bh[nt][1]);
            }
        }
        __syncthreads();
    }

    // ---- epilogue: add bias, write fp32 ----
    #pragma unroll
    for (int mt = 0; mt < 4; mt++) {
        int r = bm + wm * 64 + mt * 16 + (lane >> 2);
        #pragma unroll
        for (int nt = 0; nt < 4; nt++) {
            int cidx = bn + wn * 32 + nt * 8 + (lane & 3) * 2;
            float2 bv = *(const float2*)&bias[cidx];
            float2 o0 = { acc[mt][nt][0] + bv.x, acc[mt][nt][1] + bv.y };
            float2 o1 = { acc[mt][nt][2] + bv.x, acc[mt][nt][3] + bv.y };
            *(float2*)&C[(size_t)r * N + cidx]       = o0;
            *(float2*)&C[(size_t)(r + 8) * N + cidx] = o1;
        }
    }
}

// ---------------------------------------------------------------------------
// Flash attention (causal), fp32 (unchanged — tensor-core conversion next).
// ---------------------------------------------------------------------------
#define QS_OFF   0
#define KT_OFF   (64 * 65)
#define VS_OFF   (2 * 64 * 65)
#define PS_OFF   (2 * 64 * 65 + 64 * 64)
#define SMEM_FLOATS (2 * 64 * 65 + 64 * 64 + 64 * 65)   // 66304 B

__global__ void __launch_bounds__(256) flash_attn_kernel(
    const float* __restrict__ qkv, float* __restrict__ y)
{
    extern __shared__ float sm[];
    float* Qs = sm + QS_OFF;
    float* Kt = sm + KT_OFF;
    float* Vs = sm + VS_OFF;
    float* Ps = sm + PS_OFF;

    const int qb = blockIdx.x;
    const int h  = blockIdx.y;
    const int b  = blockIdx.z;
    const int tid = threadIdx.x;
    const int tx = tid & 15, ty = tid >> 4;
    const int r0 = ty * 4;
    const float scale = 0.125f;

    {
        const int lr = tid >> 2;
        const int lcb = (tid & 3) * 16;
        const float* gq = qkv + ((size_t)(b * SS + qb * 64 + lr)) * N_QKV + h * HDD + lcb;
        #pragma unroll
        for (int i = 0; i < 4; i++) {
            float4 v = *(const float4*)(gq + 4 * i);
            float* qs = &Qs[lr * 65 + lcb + 4 * i];
            qs[0] = v.x * scale; qs[1] = v.y * scale;
            qs[2] = v.z * scale; qs[3] = v.w * scale;
        }
    }

    float acc[4][4];
    float m_i[4], l_i[4];
    #pragma unroll
    for (int i = 0; i < 4; i++) {
        m_i[i] = -1e30f; l_i[i] = 0.0f;
        #pragma unroll
        for (int j = 0; j < 4; j++) acc[i][j] = 0.0f;
    }

    for (int kb = 0; kb <= qb; kb++) {
        {
            const int lr = tid >> 2;
            const int lcb = (tid & 3) * 16;
            const float* kg = qkv + ((size_t)(b * SS + kb * 64 + lr)) * N_QKV + h * HDD + DD + lcb;
            const float* vg = kg + DD;
            #pragma unroll
            for (int i = 0; i < 4; i++) {
                float4 kv4 = *(const float4*)(kg + 4 * i);
                Kt[(lcb + 4 * i + 0) * 65 + lr] = kv4.x;
                Kt[(lcb + 4 * i + 1) * 65 + lr] = kv4.y;
                Kt[(lcb + 4 * i + 2) * 65 + lr] = kv4.z;
                Kt[(lcb + 4 * i + 3) * 65 + lr] = kv4.w;
                float4 vv = *(const float4*)(vg + 4 * i);
                *(float4*)(&Vs[lr * 64 + lcb + 4 * i]) = vv;
            }
        }
        __syncthreads();

        float sv[4][4];
        #pragma unroll
        for (int i = 0; i < 4; i++)
            #pragma unroll
            for (int j = 0; j < 4; j++) sv[i][j] = 0.0f;

        #pragma unroll 16
        for (int k = 0; k < 64; k++) {
            float a[4], bb2[4];
            #pragma unroll
            for (int i = 0; i < 4; i++) a[i] = Qs[(r0 + i) * 65 + k];
            #pragma unroll
            for (int j = 0; j < 4; j++) bb2[j] = Kt[k * 65 + tx + 16 * j];
            #pragma unroll
            for (int i = 0; i < 4; i++)
                #pragma unroll
                for (int j = 0; j < 4; j++)
                    sv[i][j] += a[i] * bb2[j];
        }

        if (kb == qb) {
            #pragma unroll
            for (int i = 0; i < 4; i++)
                #pragma unroll
                for (int j = 0; j < 4; j++)
                    if (tx + 16 * j > r0 + i) sv[i][j] = -1e30f;
        }

        #pragma unroll
        for (int i = 0; i < 4; i++) {
            float mx = fmaxf(fmaxf(sv[i][0], sv[i][1]), fmaxf(sv[i][2], sv[i][3]));
            #pragma unroll
            for (int o = 8; o >= 1; o >>= 1)
                mx = fmaxf(mx, __shfl_xor_sync(0xffffffffu, mx, o));
            float mnew = fmaxf(m_i[i], mx);
            float p0 = __expf(sv[i][0] - mnew);
            float p1 = __expf(sv[i][1] - mnew);
            float p2 = __expf(sv[i][2] - mnew);
            float p3 = __expf(sv[i][3] - mnew);
            float ps = p0 + p1 + p2 + p3;
            #pragma unroll
            for (int o = 8; o >= 1; o >>= 1)
                ps += __shfl_xor_sync(0xffffffffu, ps, o);
            float alpha = __expf(m_i[i] - mnew);
            l_i[i] = l_i[i] * alpha + ps;
            m_i[i] = mnew;
            acc[i][0] *= alpha; acc[i][1] *= alpha;
            acc[i][2] *= alpha; acc[i][3] *= alpha;
            Ps[(r0 + i) * 65 + tx]      = p0;
            Ps[(r0 + i) * 65 + tx + 16] = p1;
            Ps[(r0 + i) * 65 + tx + 32] = p2;
            Ps[(r0 + i) * 65 + tx + 48] = p3;
        }
        __syncthreads();

        #pragma unroll 16
        for (int j = 0; j < 64; j++) {
            float p[4], v[4];
            #pragma unroll
            for (int i = 0; i < 4; i++) p[i] = Ps[(r0 + i) * 65 + j];
            #pragma unroll
            for (int c = 0; c < 4; c++) v[c] = Vs[j * 64 + tx + 16 * c];
            #pragma unroll
            for (int i = 0; i < 4; i++)
                #pragma unroll
                for (int c = 0; c < 4; c++)
                    acc[i][c] += p[i] * v[c];
        }
        __syncthreads();
    }

    #pragma unroll
    for (int i = 0; i < 4; i++) {
        float inv = 1.0f / l_i[i];
        float* yr = y + ((size_t)(b * SS + qb * 64 + r0 + i)) * DD + h * HDD;
        yr[tx]      = acc[i][0] * inv;
        yr[tx + 16] = acc[i][1] * inv;
        yr[tx + 32] = acc[i][2] * inv;
        yr[tx + 48] = acc[i][3] * inv;
    }
}

// ---------------------------------------------------------------------------
extern "C" void kernel_launch(void* const* d_in, const int* in_sizes, int n_in,
                              void* d_out, int out_size)
{
    const float* x      = (const float*)d_in[0];
    const float* W_attn = (const float*)d_in[1];
    const float* b_attn = (const float*)d_in[2];
    const float* W_proj = (const float*)d_in[3];
    const float* b_proj = (const float*)d_in[4];
    float* out = (float*)d_out;

    float *qkv, *yb;
    __nv_bfloat16 *x_hi, *x_lo, *wa_hi, *wa_lo, *wp_hi, *wp_lo, *y_hi, *y_lo;
    cudaGetSymbolAddress((void**)&qkv,   g_qkv);
    cudaGetSymbolAddress((void**)&yb,    g_y);
    cudaGetSymbolAddress((void**)&x_hi,  g_x_hi);
    cudaGetSymbolAddress((void**)&x_lo,  g_x_lo);
    cudaGetSymbolAddress((void**)&wa_hi, g_wa_hi);
    cudaGetSymbolAddress((void**)&wa_lo, g_wa_lo);
    cudaGetSymbolAddress((void**)&wp_hi, g_wp_hi);
    cudaGetSymbolAddress((void**)&wp_lo, g_wp_lo);
    cudaGetSymbolAddress((void**)&y_hi,  g_y_hi);
    cudaGetSymbolAddress((void**)&y_lo,  g_y_lo);

    cudaFuncSetAttribute(flash_attn_kernel,
                         cudaFuncAttributeMaxDynamicSharedMemorySize,
                         SMEM_FLOATS * sizeof(float));
    cudaFuncSetAttribute(gemm_bias_tc,
                         cudaFuncAttributeMaxDynamicSharedMemorySize,
                         GEMM_SMEM_BYTES);

    // 0) split fp32 inputs into bf16 hi/lo
    {
        int n4 = (M_TOT * DD) / 4;
        split_kernel<<<(n4 + 255) / 256, 256>>>(x, x_hi, x_lo, n4);
        n4 = (DD * N_QKV) / 4;
        split_kernel<<<(n4 + 255) / 256, 256>>>(W_attn, wa_hi, wa_lo, n4);
        n4 = (DD * DD) / 4;
        split_kernel<<<(n4 + 255) / 256, 256>>>(W_proj, wp_hi, wp_lo, n4);
    }

    // 1) QKV projection
    {
        dim3 grid(N_QKV / 128, M_TOT / 128);
        gemm_bias_tc<<<grid, 256, GEMM_SMEM_BYTES>>>(
            x_hi, x_lo, wa_hi, wa_lo, b_attn, qkv, M_TOT, N_QKV, DD);
    }

    // 2) causal flash attention -> y
    {
        dim3 grid(SS / 64, HH, BB);
        flash_attn_kernel<<<grid, 256, SMEM_FLOATS * sizeof(float)>>>(qkv, yb);
    }

    // 2b) split y
    {
        int n4 = (M_TOT * DD) / 4;
        split_kernel<<<(n4 + 255) / 256, 256>>>(yb, y_hi, y_lo, n4);
    }

    // 3) output projection
    {
        dim3 grid(DD / 128, M_TOT / 128);
        gemm_bias_tc<<<grid, 256, GEMM_SMEM_BYTES>>>(
            y_hi, y_lo, wp_hi, wp_lo, b_proj, out, M_TOT, DD, DD);
    }
}

// round 5
// speedup vs baseline: 2.8979x; 1.8392x over previous
#include <cuda_runtime.h>
#include <cuda_bf16.h>
#include <math.h>
#include <stdint.h>

#define BB 4
#define SS 2048
#define DD 1024
#define HH 16
#define HDD 64
#define M_TOT (BB*SS)          // 8192
#define N_QKV (3*DD)           // 3072

// ---------------- device scratch (allocation-free) ----------------
__device__ __nv_bfloat16 g_qkv_hi[(size_t)M_TOT * N_QKV];
__device__ __nv_bfloat16 g_qkv_lo[(size_t)M_TOT * N_QKV];
__device__ __nv_bfloat16 g_x_hi[(size_t)M_TOT * DD];
__device__ __nv_bfloat16 g_x_lo[(size_t)M_TOT * DD];
__device__ __nv_bfloat16 g_wa_hi[(size_t)DD * N_QKV];
__device__ __nv_bfloat16 g_wa_lo[(size_t)DD * N_QKV];
__device__ __nv_bfloat16 g_wp_hi[(size_t)DD * DD];
__device__ __nv_bfloat16 g_wp_lo[(size_t)DD * DD];
__device__ __nv_bfloat16 g_y_hi[(size_t)M_TOT * DD];
__device__ __nv_bfloat16 g_y_lo[(size_t)M_TOT * DD];

// ---------------- small PTX helpers ----------------
__device__ __forceinline__ void cp16(uint32_t dst, const void* src) {
    asm volatile("cp.async.cg.shared.global [%0], [%1], 16;" :: "r"(dst), "l"(src));
}
#define CP_COMMIT() asm volatile("cp.async.commit_group;")
#define CP_WAIT0()  asm volatile("cp.async.wait_group 0;")

__device__ __forceinline__ void ldsm_x4(uint32_t addr,
    uint32_t& r0, uint32_t& r1, uint32_t& r2, uint32_t& r3) {
    asm volatile("ldmatrix.sync.aligned.m8n8.x4.shared.b16 {%0,%1,%2,%3}, [%4];"
        : "=r"(r0), "=r"(r1), "=r"(r2), "=r"(r3) : "r"(addr));
}
__device__ __forceinline__ void ldsm_x4_t(uint32_t addr,
    uint32_t& r0, uint32_t& r1, uint32_t& r2, uint32_t& r3) {
    asm volatile("ldmatrix.sync.aligned.m8n8.x4.trans.shared.b16 {%0,%1,%2,%3}, [%4];"
        : "=r"(r0), "=r"(r1), "=r"(r2), "=r"(r3) : "r"(addr));
}
__device__ __forceinline__ void mma_bf16(float* d,
    uint32_t a0, uint32_t a1, uint32_t a2, uint32_t a3,
    uint32_t b0, uint32_t b1)
{
    asm volatile(
        "mma.sync.aligned.m16n8k16.row.col.f32.bf16.bf16.f32 "
        "{%0,%1,%2,%3}, {%4,%5,%6,%7}, {%8,%9}, {%0,%1,%2,%3};\n"
        : "+f"(d[0]), "+f"(d[1]), "+f"(d[2]), "+f"(d[3])
        : "r"(a0), "r"(a1), "r"(a2), "r"(a3), "r"(b0), "r"(b1));
}
__device__ __forceinline__ void pack_split(float x, float y, uint32_t& hi, uint32_t& lo) {
    __nv_bfloat162 h = __floats2bfloat162_rn(x, y);
    hi = *(uint32_t*)&h;
    float rx = x - __bfloat162float(h.x);
    float ry = y - __bfloat162float(h.y);
    __nv_bfloat162 l = __floats2bfloat162_rn(rx, ry);
    lo = *(uint32_t*)&l;
}

// ---------------- split pass: fp32 -> (bf16 hi, bf16 lo) ----------------
__global__ void __launch_bounds__(256) split_kernel(
    const float* __restrict__ in,
    __nv_bfloat16* __restrict__ hi, __nv_bfloat16* __restrict__ lo, int n4)
{
    int i = blockIdx.x * blockDim.x + threadIdx.x;
    if (i >= n4) return;
    float4 v = ((const float4*)in)[i];
    uint32_t h0, l0, h1, l1;
    pack_split(v.x, v.y, h0, l0);
    pack_split(v.z, v.w, h1, l1);
    ((uint32_t*)hi)[2*i]   = h0;
    ((uint32_t*)hi)[2*i+1] = h1;
    ((uint32_t*)lo)[2*i]   = l0;
    ((uint32_t*)lo)[2*i+1] = l1;
}

// ---------------------------------------------------------------------------
// Tensor-core split-bf16 GEMM. SPLIT_OUT=1: write hi/lo bf16; else fp32.
// ---------------------------------------------------------------------------
#define A_STR 40
#define B_STR 136
#define AH_OFF 0
#define AL_OFF (128*A_STR)
#define BH_OFF (2*128*A_STR)
#define BL_OFF (2*128*A_STR + 32*B_STR)
#define STAGE_ELEMS (2*128*A_STR + 2*32*B_STR)
#define GEMM_SMEM_BYTES (2 * STAGE_ELEMS * 2)

template<int SPLIT_OUT>
__global__ void __launch_bounds__(256, 2) gemm_bias_tc(
    const __nv_bfloat16* __restrict__ Ahi, const __nv_bfloat16* __restrict__ Alo,
    const __nv_bfloat16* __restrict__ Whi, const __nv_bfloat16* __restrict__ Wlo,
    const float* __restrict__ bias, float* __restrict__ C,
    __nv_bfloat16* __restrict__ Chi, __nv_bfloat16* __restrict__ Clo,
    int M, int N, int K)
{
    extern __shared__ __nv_bfloat16 smem[];
    const uint32_t smem_u32 = (uint32_t)__cvta_generic_to_shared(smem);

    const int tid  = threadIdx.x;
    const int lane = tid & 31;
    const int warp = tid >> 5;
    const int wm   = warp >> 2;
    const int wn   = warp & 3;
    const int bm   = blockIdx.y * 128;
    const int bn   = blockIdx.x * 128;

    const int ar = tid >> 1;
    const int aj = (tid & 1) * 16;
    const int kr = tid >> 3;
    const int bj = (tid & 7) * 16;

    const __nv_bfloat16* Ahi_g = Ahi + (size_t)(bm + ar) * K + aj;
    const __nv_bfloat16* Alo_g = Alo + (size_t)(bm + ar) * K + aj;
    const __nv_bfloat16* Whi_g = Whi + (size_t)kr * N + bn + bj;
    const __nv_bfloat16* Wlo_g = Wlo + (size_t)kr * N + bn + bj;

    const uint32_t a_sm = smem_u32 + (ar * A_STR + aj) * 2;
    const uint32_t b_sm = smem_u32 + (kr * B_STR + bj) * 2;

    auto issue_stage = [&](int k0, int s) {
        const uint32_t so = (uint32_t)(s * STAGE_ELEMS * 2);
        cp16(so + a_sm + AH_OFF*2,      Ahi_g + k0);
        cp16(so + a_sm + AH_OFF*2 + 16, Ahi_g + k0 + 8);
        cp16(so + a_sm + AL_OFF*2,      Alo_g + k0);
        cp16(so + a_sm + AL_OFF*2 + 16, Alo_g + k0 + 8);
        cp16(so + b_sm + BH_OFF*2,      Whi_g + (size_t)k0 * N);
        cp16(so + b_sm + BH_OFF*2 + 16, Whi_g + (size_t)k0 * N + 8);
        cp16(so + b_sm + BL_OFF*2,      Wlo_g + (size_t)k0 * N);
        cp16(so + b_sm + BL_OFF*2 + 16, Wlo_g + (size_t)k0 * N + 8);
        CP_COMMIT();
    };

    float acc[4][4][4];
    #pragma unroll
    for (int mt = 0; mt < 4; mt++)
        #pragma unroll
        for (int nt = 0; nt < 4; nt++)
            #pragma unroll
            for (int r = 0; r < 4; r++) acc[mt][nt][r] = 0.0f;

    const int a_row_in = (lane & 7) + ((lane >> 3) & 1) * 8;
    const int a_kcol   = (lane >> 4) * 8;
    const int b_krow   = ((lane >> 3) & 1) * 8 + (lane & 7);
    const int b_ncol   = (lane >> 4) * 8;

    issue_stage(0, 0);

    const int nt_iters = K / 32;
    for (int t = 0; t < nt_iters; t++) {
        CP_WAIT0();
        __syncthreads();
        if (t + 1 < nt_iters) issue_stage((t + 1) * 32, (t + 1) & 1);

        const uint32_t so = (uint32_t)((t & 1) * STAGE_ELEMS * 2);
        const uint32_t ah_base = smem_u32 + so + AH_OFF * 2;
        const uint32_t al_base = smem_u32 + so + AL_OFF * 2;
        const uint32_t bh_base = smem_u32 + so + BH_OFF * 2;
        const uint32_t bl_base = smem_u32 + so + BL_OFF * 2;

        #pragma unroll
        for (int kk = 0; kk < 32; kk += 16) {
            uint32_t bh[4][2], bl[4][2];
            #pragma unroll
            for (int p = 0; p < 2; p++) {
                const uint32_t baddr = (uint32_t)(((kk + b_krow) * B_STR +
                                       wn * 32 + p * 16 + b_ncol) * 2);
                ldsm_x4_t(bh_base + baddr, bh[2*p][0], bh[2*p][1], bh[2*p+1][0], bh[2*p+1][1]);
                ldsm_x4_t(bl_base + baddr, bl[2*p][0], bl[2*p][1], bl[2*p+1][0], bl[2*p+1][1]);
            }
            #pragma unroll
            for (int mt = 0; mt < 4; mt++) {
                const uint32_t aaddr = (uint32_t)(((wm * 64 + mt * 16 + a_row_in) * A_STR +
                                       kk + a_kcol) * 2);
                uint32_t ah0, ah1, ah2, ah3, al0, al1, al2, al3;
                ldsm_x4(ah_base + aaddr, ah0, ah1, ah2, ah3);
                ldsm_x4(al_base + aaddr, al0, al1, al2, al3);
                #pragma unroll
                for (int nt = 0; nt < 4; nt++)
                    mma_bf16(acc[mt][nt], ah0, ah1, ah2, ah3, bh[nt][0], bh[nt][1]);
                #pragma unroll
                for (int nt = 0; nt < 4; nt++)
                    mma_bf16(acc[mt][nt], ah0, ah1, ah2, ah3, bl[nt][0], bl[nt][1]);
                #pragma unroll
                for (int nt = 0; nt < 4; nt++)
                    mma_bf16(acc[mt][nt], al0, al1, al2, al3, bh[nt][0], bh[nt][1]);
            }
        }
        __syncthreads();
    }

    #pragma unroll
    for (int mt = 0; mt < 4; mt++) {
        int r = bm + wm * 64 + mt * 16 + (lane >> 2);
        #pragma unroll
        for (int nt = 0; nt < 4; nt++) {
            int cidx = bn + wn * 32 + nt * 8 + (lane & 3) * 2;
            float2 bv = *(const float2*)&bias[cidx];
            float o0 = acc[mt][nt][0] + bv.x;
            float o1 = acc[mt][nt][1] + bv.y;
            float o2 = acc[mt][nt][2] + bv.x;
            float o3 = acc[mt][nt][3] + bv.y;
            if (SPLIT_OUT) {
                uint32_t h0, l0, h1, l1;
                pack_split(o0, o1, h0, l0);
                pack_split(o2, o3, h1, l1);
                *(uint32_t*)&Chi[(size_t)r * N + cidx]       = h0;
                *(uint32_t*)&Clo[(size_t)r * N + cidx]       = l0;
                *(uint32_t*)&Chi[(size_t)(r + 8) * N + cidx] = h1;
                *(uint32_t*)&Clo[(size_t)(r + 8) * N + cidx] = l1;
            } else {
                float2 w0 = { o0, o1 }, w1 = { o2, o3 };
                *(float2*)&C[(size_t)r * N + cidx]       = w0;
                *(float2*)&C[(size_t)(r + 8) * N + cidx] = w1;
            }
        }
    }
}

// ---------------------------------------------------------------------------
// Tensor-core causal flash attention, split-bf16 (3-product) for S and PV.
// Grid (S/128, H, B), 256 threads (8 warps x m16). Keys in 64-chunks.
// smem (bf16 elems, stride 72): Qhi[128][72], Qlo, Khi[64][72], Klo, Vhi, Vlo
// ---------------------------------------------------------------------------
#define ASTR 72
#define QH_OFF 0
#define QL_OFF (128*ASTR)              // 9216
#define KH_OFF (2*128*ASTR)            // 18432
#define KL_OFF (2*128*ASTR + 64*ASTR)  // 23040
#define VH_OFF (2*128*ASTR + 2*64*ASTR)// 27648
#define VL_OFF (2*128*ASTR + 3*64*ASTR)// 32256
#define ATT_SMEM_ELEMS (2*128*ASTR + 4*64*ASTR)  // 36864
#define ATT_SMEM_BYTES (ATT_SMEM_ELEMS * 2)      // 73728

__global__ void __launch_bounds__(256, 2) flash_attn_tc(
    const __nv_bfloat16* __restrict__ qkvh, const __nv_bfloat16* __restrict__ qkvl,
    __nv_bfloat16* __restrict__ yh, __nv_bfloat16* __restrict__ yl)
{
    extern __shared__ __nv_bfloat16 sm_att[];
    const uint32_t smb = (uint32_t)__cvta_generic_to_shared(sm_att);

    const int qb = blockIdx.x;
    const int h  = blockIdx.y;
    const int b  = blockIdx.z;
    const int tid  = threadIdx.x;
    const int lane = tid & 31;
    const int warp = tid >> 5;
    const int m0   = warp * 16;
    const int q0   = qb * 128;
    const float scale = 0.125f;

    // ---- load Q tile (hi/lo) via cp.async ----
    {
        const int row  = tid >> 1;
        const int colb = (tid & 1) * 32;
        const size_t base = ((size_t)(b * SS + q0 + row)) * N_QKV + h * HDD + colb;
        const uint32_t dh = smb + (QH_OFF + row * ASTR + colb) * 2;
        const uint32_t dl = smb + (QL_OFF + row * ASTR + colb) * 2;
        #pragma unroll
        for (int c = 0; c < 4; c++) {
            cp16(dh + c * 16, qkvh + base + c * 8);
            cp16(dl + c * 16, qkvl + base + c * 8);
        }
        CP_COMMIT();
    }

    float o[8][4];
    float s[8][4];
    float mrow[2] = { -1e30f, -1e30f };
    float lrow[2] = { 0.0f, 0.0f };
    #pragma unroll
    for (int i = 0; i < 8; i++)
        #pragma unroll
        for (int j = 0; j < 4; j++) o[i][j] = 0.0f;

    // ldmatrix lane addressing
    const int a_row = (lane & 7) + ((lane >> 3) & 1) * 8;  // A (Q / row-major)
    const int a_k   = (lane >> 4) * 8;
    const int kb_n  = (lane & 7) + ((lane >> 4) & 1) * 8;  // K as B, [n][k] non-trans
    const int kb_k  = ((lane >> 3) & 1) * 8;
    const int vb_k  = ((lane >> 3) & 1) * 8 + (lane & 7);  // V as B, [k][n] trans
    const int vb_n  = (lane >> 4) * 8;

    const int r_in  = lane >> 2;       // row within m8
    const int c_in  = (lane & 3) * 2;  // col pair

    const int kmax = 2 * qb + 1;

    for (int kb = 0; kb <= kmax; kb++) {
        __syncthreads();   // previous iteration's K/V reads complete
        // ---- load K/V (hi/lo) ----
        {
            const int row  = tid >> 2;
            const int colb = (tid & 3) * 16;
            const size_t base = ((size_t)(b * SS + kb * 64 + row)) * N_QKV + h * HDD + colb;
            const uint32_t dkh = smb + (KH_OFF + row * ASTR + colb) * 2;
            const uint32_t dkl = smb + (KL_OFF + row * ASTR + colb) * 2;
            const uint32_t dvh = smb + (VH_OFF + row * ASTR + colb) * 2;
            const uint32_t dvl = smb + (VL_OFF + row * ASTR + colb) * 2;
            #pragma unroll
            for (int c = 0; c < 2; c++) {
                cp16(dkh + c * 16, qkvh + base + DD     + c * 8);
                cp16(dkl + c * 16, qkvl + base + DD     + c * 8);
                cp16(dvh + c * 16, qkvh + base + 2 * DD + c * 8);
                cp16(dvl + c * 16, qkvl + base + 2 * DD + c * 8);
            }
            CP_COMMIT();
        }
        CP_WAIT0();
        __syncthreads();

        // ---- S = Q K^T (split-bf16, 3 products) ----
        #pragma unroll
        for (int i = 0; i < 8; i++)
            #pragma unroll
            for (int j = 0; j < 4; j++) s[i][j] = 0.0f;

        #pragma unroll
        for (int kk = 0; kk < 64; kk += 16) {
            uint32_t qh0, qh1, qh2, qh3, ql0, ql1, ql2, ql3;
            const uint32_t qaddr = (uint32_t)(((m0 + a_row) * ASTR + kk + a_k) * 2);
            ldsm_x4(smb + QH_OFF * 2 + qaddr, qh0, qh1, qh2, qh3);
            ldsm_x4(smb + QL_OFF * 2 + qaddr, ql0, ql1, ql2, ql3);
            #pragma unroll
            for (int np = 0; np < 4; np++) {
                uint32_t kh0, kh1, kh2, kh3, kl0, kl1, kl2, kl3;
                const uint32_t kaddr = (uint32_t)(((np * 16 + kb_n) * ASTR + kk + kb_k) * 2);
                ldsm_x4(smb + KH_OFF * 2 + kaddr, kh0, kh1, kh2, kh3);
                ldsm_x4(smb + KL_OFF * 2 + kaddr, kl0, kl1, kl2, kl3);
                mma_bf16(s[2*np],   qh0, qh1, qh2, qh3, kh0, kh1);
                mma_bf16(s[2*np],   qh0, qh1, qh2, qh3, kl0, kl1);
                mma_bf16(s[2*np],   ql0, ql1, ql2, ql3, kh0, kh1);
                mma_bf16(s[2*np+1], qh0, qh1, qh2, qh3, kh2, kh3);
                mma_bf16(s[2*np+1], qh0, qh1, qh2, qh3, kl2, kl3);
                mma_bf16(s[2*np+1], ql0, ql1, ql2, ql3, kh2, kh3);
            }
        }

        // ---- scale + causal mask + row max ----
        const bool masked = (kb >= 2 * qb);
        float alpha[2];
        #pragma unroll
        for (int r = 0; r < 2; r++) {
            const int rowg = q0 + m0 + r_in + 8 * r;
            float mx = -1e30f;
            #pragma unroll
            for (int nt = 0; nt < 8; nt++) {
                #pragma unroll
                for (int c = 0; c < 2; c++) {
                    float t = s[nt][2*r + c] * scale;
                    if (masked) {
                        int keyg = kb * 64 + nt * 8 + c_in + c;
                        if (keyg > rowg) t = -1e30f;
                    }
                    s[nt][2*r + c] = t;
                    mx = fmaxf(mx, t);
                }
            }
            mx = fmaxf(mx, __shfl_xor_sync(0xffffffffu, mx, 1));
            mx = fmaxf(mx, __shfl_xor_sync(0xffffffffu, mx, 2));
            float mnew = fmaxf(mrow[r], mx);
            alpha[r] = __expf(mrow[r] - mnew);
            mrow[r] = mnew;
            float ps = 0.0f;
            #pragma unroll
            for (int nt = 0; nt < 8; nt++) {
                #pragma unroll
                for (int c = 0; c < 2; c++) {
                    float p = __expf(s[nt][2*r + c] - mnew);
                    s[nt][2*r + c] = p;
                    ps += p;
                }
            }
            lrow[r] = lrow[r] * alpha[r] + ps;
        }
        #pragma unroll
        for (int nh = 0; nh < 8; nh++) {
            o[nh][0] *= alpha[0]; o[nh][1] *= alpha[0];
            o[nh][2] *= alpha[1]; o[nh][3] *= alpha[1];
        }

        // ---- O += P V (split-bf16, 3 products); P frags from registers ----
        #pragma unroll
        for (int kt = 0; kt < 4; kt++) {
            uint32_t ph[4], pl[4];
            pack_split(s[2*kt][0],   s[2*kt][1],   ph[0], pl[0]);
            pack_split(s[2*kt][2],   s[2*kt][3],   ph[1], pl[1]);
            pack_split(s[2*kt+1][0], s[2*kt+1][1], ph[2], pl[2]);
            pack_split(s[2*kt+1][2], s[2*kt+1][3], ph[3], pl[3]);
            #pragma unroll
            for (int np = 0; np < 4; np++) {
                uint32_t vh0, vh1, vh2, vh3, vl0, vl1, vl2, vl3;
                const uint32_t vaddr = (uint32_t)(((kt * 16 + vb_k) * ASTR + np * 16 + vb_n) * 2);
                ldsm_x4_t(smb + VH_OFF * 2 + vaddr, vh0, vh1, vh2, vh3);
                ldsm_x4_t(smb + VL_OFF * 2 + vaddr, vl0, vl1, vl2, vl3);
                mma_bf16(o[2*np],   ph[0], ph[1], ph[2], ph[3], vh0, vh1);
                mma_bf16(o[2*np],   ph[0], ph[1], ph[2], ph[3], vl0, vl1);
                mma_bf16(o[2*np],   pl[0], pl[1], pl[2], pl[3], vh0, vh1);
                mma_bf16(o[2*np+1], ph[0], ph[1], ph[2], ph[3], vh2, vh3);
                mma_bf16(o[2*np+1], ph[0], ph[1], ph[2], ph[3], vl2, vl3);
                mma_bf16(o[2*np+1], pl[0], pl[1], pl[2], pl[3], vh2, vh3);
            }
        }
    }

    // ---- epilogue ----
    float inv[2];
    #pragma unroll
    for (int r = 0; r < 2; r++) {
        lrow[r] += __shfl_xor_sync(0xffffffffu, lrow[r], 1);
        lrow[r] += __shfl_xor_sync(0xffffffffu, lrow[r], 2);
        inv[r] = 1.0f / lrow[r];
    }
    #pragma unroll
    for (int nh = 0; nh < 8; nh++) {
        #pragma unroll
        for (int r = 0; r < 2; r++) {
            float a0 = o[nh][2*r]     * inv[r];
            float a1 = o[nh][2*r + 1] * inv[r];
            uint32_t hi, lo;
            pack_split(a0, a1, hi, lo);
            const size_t row = (size_t)(b * SS + q0 + m0 + r_in + 8 * r);
            const int col = h * HDD + nh * 8 + c_in;
            *(uint32_t*)&yh[row * DD + col] = hi;
            *(uint32_t*)&yl[row * DD + col] = lo;
        }
    }
}

// ---------------------------------------------------------------------------
extern "C" void kernel_launch(void* const* d_in, const int* in_sizes, int n_in,
                              void* d_out, int out_size)
{
    const float* x      = (const float*)d_in[0];
    const float* W_attn = (const float*)d_in[1];
    const float* b_attn = (const float*)d_in[2];
    const float* W_proj = (const float*)d_in[3];
    const float* b_proj = (const float*)d_in[4];
    float* out = (float*)d_out;

    __nv_bfloat16 *qkv_hi, *qkv_lo, *x_hi, *x_lo, *wa_hi, *wa_lo, *wp_hi, *wp_lo, *y_hi, *y_lo;
    cudaGetSymbolAddress((void**)&qkv_hi, g_qkv_hi);
    cudaGetSymbolAddress((void**)&qkv_lo, g_qkv_lo);
    cudaGetSymbolAddress((void**)&x_hi,  g_x_hi);
    cudaGetSymbolAddress((void**)&x_lo,  g_x_lo);
    cudaGetSymbolAddress((void**)&wa_hi, g_wa_hi);
    cudaGetSymbolAddress((void**)&wa_lo, g_wa_lo);
    cudaGetSymbolAddress((void**)&wp_hi, g_wp_hi);
    cudaGetSymbolAddress((void**)&wp_lo, g_wp_lo);
    cudaGetSymbolAddress((void**)&y_hi,  g_y_hi);
    cudaGetSymbolAddress((void**)&y_lo,  g_y_lo);

    cudaFuncSetAttribute(gemm_bias_tc<0>,
                         cudaFuncAttributeMaxDynamicSharedMemorySize, GEMM_SMEM_BYTES);
    cudaFuncSetAttribute(gemm_bias_tc<1>,
                         cudaFuncAttributeMaxDynamicSharedMemorySize, GEMM_SMEM_BYTES);
    cudaFuncSetAttribute(flash_attn_tc,
                         cudaFuncAttributeMaxDynamicSharedMemorySize, ATT_SMEM_BYTES);

    // 0) split fp32 inputs into bf16 hi/lo
    {
        int n4 = (M_TOT * DD) / 4;
        split_kernel<<<(n4 + 255) / 256, 256>>>(x, x_hi, x_lo, n4);
        n4 = (DD * N_QKV) / 4;
        split_kernel<<<(n4 + 255) / 256, 256>>>(W_attn, wa_hi, wa_lo, n4);
        n4 = (DD * DD) / 4;
        split_kernel<<<(n4 + 255) / 256, 256>>>(W_proj, wp_hi, wp_lo, n4);
    }

    // 1) QKV projection -> qkv hi/lo (bf16 split written directly)
    {
        dim3 grid(N_QKV / 128, M_TOT / 128);
        gemm_bias_tc<1><<<grid, 256, GEMM_SMEM_BYTES>>>(
            x_hi, x_lo, wa_hi, wa_lo, b_attn, nullptr, qkv_hi, qkv_lo,
            M_TOT, N_QKV, DD);
    }

    // 2) tensor-core causal flash attention -> y hi/lo
    {
        dim3 grid(SS / 128, HH, BB);
        flash_attn_tc<<<grid, 256, ATT_SMEM_BYTES>>>(qkv_hi, qkv_lo, y_hi, y_lo);
    }

    // 3) output projection -> fp32 out
    {
        dim3 grid(DD / 128, M_TOT / 128);
        gemm_bias_tc<0><<<grid, 256, GEMM_SMEM_BYTES>>>(
            y_hi, y_lo, wp_hi, wp_lo, b_proj, out, nullptr, nullptr,
            M_TOT, DD, DD);
    }
}